// round 15
// baseline (speedup 1.0000x reference)
#include <cuda_runtime.h>
#include <cuda_fp16.h>
#include <math.h>
#include <cstdint>

#define D_MODEL   1024
#define T_SEQ     2048
#define B_SZ      4
#define N_HEADS   16
#define HEAD_DIM  64
#define M_ROWS    8192
#define QKV_N     3072

// Scratch (no cudaMalloc allowed)
__device__ __half  g_qkv_h[(size_t)M_ROWS * QKV_N];
__device__ __half  g_x_h[(size_t)M_ROWS * D_MODEL];
__device__ __half  g_att_h[(size_t)M_ROWS * D_MODEL];
__device__ __half  g_wqkv_h[(size_t)QKV_N * D_MODEL];
__device__ __half  g_wout_h[(size_t)D_MODEL * D_MODEL];

__device__ __forceinline__ uint32_t smem_u32(const void* p) {
    uint32_t a;
    asm("{ .reg .u64 t; cvta.to.shared.u64 t, %1; cvt.u32.u64 %0, t; }" : "=r"(a) : "l"(p));
    return a;
}
__device__ __forceinline__ uint32_t pack_h2(float a, float b) {
    __half2 v = __floats2half2_rn(a, b);
    return *reinterpret_cast<uint32_t*>(&v);
}

#define LDSM4(r, addr) \
    asm volatile("ldmatrix.sync.aligned.m8n8.x4.shared.b16 {%0,%1,%2,%3}, [%4];" \
        : "=r"((r)[0]), "=r"((r)[1]), "=r"((r)[2]), "=r"((r)[3]) : "r"(addr))
#define LDSM4T(r, addr) \
    asm volatile("ldmatrix.sync.aligned.m8n8.x4.trans.shared.b16 {%0,%1,%2,%3}, [%4];" \
        : "=r"((r)[0]), "=r"((r)[1]), "=r"((r)[2]), "=r"((r)[3]) : "r"(addr))

#define MMA_F16(d, a, b) \
    asm volatile("mma.sync.aligned.m16n8k16.row.col.f32.f16.f16.f32 " \
        "{%0,%1,%2,%3}, {%4,%5,%6,%7}, {%8,%9}, {%0,%1,%2,%3};" \
        : "+f"((d)[0]), "+f"((d)[1]), "+f"((d)[2]), "+f"((d)[3]) \
        : "r"((a)[0]), "r"((a)[1]), "r"((a)[2]), "r"((a)[3]), "r"((b)[0]), "r"((b)[1]))

#define CP16(dst, src) \
    asm volatile("cp.async.cg.shared.global [%0], [%1], 16;" :: "r"(dst), "l"(src) : "memory")
#define CP_COMMIT() asm volatile("cp.async.commit_group;" ::: "memory")

// ---------------------------------------------------------------------------
__global__ void cvt_x_f16(const float4* __restrict__ x,
                          __half* __restrict__ hi, int n4) {
    const int i = blockIdx.x * 256 + threadIdx.x;
    if (i >= n4) return;
    float4 v = x[i];
    uint32_t* hp = reinterpret_cast<uint32_t*>(hi) + 2 * i;
    hp[0] = pack_h2(v.x, v.y);
    hp[1] = pack_h2(v.z, v.w);
}

__global__ void transpose_f16(const float* __restrict__ W,
                              __half* __restrict__ Wt,
                              int Kr, int Nc, int scale_lim, float scale) {
    __shared__ float tile[32][33];
    const int bx = blockIdx.x * 32, by = blockIdx.y * 32;
    const int tx = threadIdx.x, ty = threadIdx.y;
#pragma unroll
    for (int u = 0; u < 32; u += 8)
        tile[ty + u][tx] = W[(size_t)(by + ty + u) * Nc + bx + tx];
    __syncthreads();
#pragma unroll
    for (int u = 0; u < 32; u += 8) {
        const int n = bx + ty + u;
        float v = tile[tx][ty + u];
        if (n < scale_lim) v *= scale;
        Wt[(size_t)n * Kr + by + tx] = __float2half_rn(v);
    }
}

// ---------------------------------------------------------------------------
// Single-term fp16 GEMM: C = A @ B^T  (fp32 acc).
// CTA 128x128, 128 threads, 4 warps 64x64; K-panel 32, 2-stage cp.async.
// ---------------------------------------------------------------------------
#define PANEL    32
#define RSTRIDE  80
#define TILE_B   (128 * RSTRIDE)        // 10240
#define SST      (2 * TILE_B)           // A, B per stage

template<bool F16OUT>
__global__ __launch_bounds__(128, 2) void f16_gemm_t(const __half* __restrict__ A,
                                                     const __half* __restrict__ B,
                                                     float* __restrict__ C,
                                                     __half* __restrict__ Ch,
                                                     int M, int N, int K) {
    extern __shared__ char sm[];
    const uint32_t base = smem_u32(sm);

    const int t = threadIdx.x;
    const int wid = t >> 5, lane = t & 31;
    const int m0 = blockIdx.y * 128, n0 = blockIdx.x * 128;
    const int wm = (wid >> 1) * 64, wn = (wid & 1) * 64;
    const int NKI = K / PANEL;

    const int rg = t >> 2, sg = t & 3;
    const uint32_t s_off = (uint32_t)(rg * RSTRIDE + sg * 16);

    auto load_stage = [&](int i, int s) {
        const size_t k0 = (size_t)i * PANEL + sg * 8;
        const uint32_t st = base + s * SST + s_off;
#pragma unroll
        for (int u = 0; u < 4; ++u) {
            const int r = rg + u * 32;
            const uint32_t so = st + u * 32 * RSTRIDE;
            CP16(so,          A + (size_t)(m0 + r) * K + k0);
            CP16(so + TILE_B, B + (size_t)(n0 + r) * K + k0);
        }
        CP_COMMIT();
    };

    uint32_t aoff[4], boff[4];
#pragma unroll
    for (int mt = 0; mt < 4; ++mt)
        aoff[mt] = (uint32_t)((wm + mt * 16 + (lane & 15)) * RSTRIDE + (lane >> 4) * 16);
#pragma unroll
    for (int p = 0; p < 4; ++p)
        boff[p] = (uint32_t)((wn + p * 16 + ((lane >> 4) << 3) + (lane & 7)) * RSTRIDE
                             + ((lane >> 3) & 1) * 16);

    float acc[4][8][4];
#pragma unroll
    for (int i = 0; i < 4; ++i)
#pragma unroll
        for (int j = 0; j < 8; ++j)
#pragma unroll
            for (int r = 0; r < 4; ++r) acc[i][j][r] = 0.0f;

    load_stage(0, 0);

    for (int i = 0; i < NKI; ++i) {
        if (i + 1 < NKI) {
            load_stage(i + 1, (i + 1) & 1);
            asm volatile("cp.async.wait_group 1;" ::: "memory");
        } else {
            asm volatile("cp.async.wait_group 0;" ::: "memory");
        }
        __syncthreads();

        const uint32_t sA = base + (i & 1) * SST;
        const uint32_t sB = sA + TILE_B;

#pragma unroll
        for (int ks = 0; ks < 2; ++ks) {
            uint32_t af[4][4];
#pragma unroll
            for (int mt = 0; mt < 4; ++mt)
                LDSM4(af[mt], sA + aoff[mt] + ks * 32);
#pragma unroll
            for (int p = 0; p < 4; ++p) {
                uint32_t bf[4];
                LDSM4(bf, sB + boff[p] + ks * 32);
#pragma unroll
                for (int j = 0; j < 2; ++j)
#pragma unroll
                    for (int mt = 0; mt < 4; ++mt)
                        MMA_F16(acc[mt][2 * p + j], af[mt], &bf[j * 2]);
            }
        }
        __syncthreads();
    }

    const int r_lo = lane >> 2, c_lo = (lane & 3) * 2;
#pragma unroll
    for (int mt = 0; mt < 4; ++mt) {
        const int row = m0 + wm + mt * 16 + r_lo;
#pragma unroll
        for (int n8 = 0; n8 < 8; ++n8) {
            const int col = n0 + wn + n8 * 8 + c_lo;
            if constexpr (F16OUT) {
                *(uint32_t*)(Ch + (size_t)row * N + col) =
                    pack_h2(acc[mt][n8][0], acc[mt][n8][1]);
                *(uint32_t*)(Ch + (size_t)(row + 8) * N + col) =
                    pack_h2(acc[mt][n8][2], acc[mt][n8][3]);
            } else {
                *(float2*)(C + (size_t)row * N + col) =
                    make_float2(acc[mt][n8][0], acc[mt][n8][1]);
                *(float2*)(C + (size_t)(row + 8) * N + col) =
                    make_float2(acc[mt][n8][2], acc[mt][n8][3]);
            }
        }
    }
}

// ---------------------------------------------------------------------------
// Tensor-core flash attention, single-fp16 operands.
// NOW 2 CTAs/SM (smem 92KB x2 fits; regs capped at 128 by launch_bounds):
// co-resident CTA's MMAs hide this CTA's softmax ALU/MUFU phase.
// ---------------------------------------------------------------------------
#define FAS    144
#define FTILE  (128 * FAS)
#define KVST   (2 * FTILE)              // Kh, Vh per stage

__global__ __launch_bounds__(256, 2) void flash_attn_tc(
    const __half* __restrict__ qkvh,
    __half* __restrict__ att_h) {
    extern __shared__ char sm[];
    const uint32_t base  = smem_u32(sm);
    const uint32_t qbase = base + 2 * KVST;   // single Q tile

    const int qi = (int)gridDim.x - 1 - (int)blockIdx.x;
    const int bh = blockIdx.y;
    const int b  = bh >> 4, h = bh & 15;
    const int t  = threadIdx.x;
    const int wid = t >> 5, lane = t & 31;

    const int rowQ0 = b * T_SEQ + qi * 128;
    const int colQ = h * HEAD_DIM;
    const int colK = D_MODEL + h * HEAD_DIM;
    const int colV = 2 * D_MODEL + h * HEAD_DIM;

    const int rg = t >> 3, sg = t & 7;
    const uint32_t ls_off = (uint32_t)(rg * FAS + sg * 16);

#define LOADKV(kt, s) do { \
        const uint32_t _st = base + (s) * KVST + ls_off; \
        _Pragma("unroll") \
        for (int _u = 0; _u < 4; ++_u) { \
            const int _r = rg + _u * 32; \
            const size_t _row = (size_t)(b * T_SEQ + (kt) * 128 + _r) * QKV_N; \
            const uint32_t _so = _st + _u * 32 * FAS; \
            CP16(_so,         qkvh + _row + colK + sg * 8); \
            CP16(_so + FTILE, qkvh + _row + colV + sg * 8); \
        } \
        CP_COMMIT(); \
    } while (0)

    {
#pragma unroll
        for (int u = 0; u < 4; ++u) {
            const int r = rg + u * 32;
            const size_t row = (size_t)(rowQ0 + r) * QKV_N;
            CP16(qbase + ls_off + u * 32 * FAS, qkvh + row + colQ + sg * 8);
        }
        CP_COMMIT();
    }
    LOADKV(0, 0);

    asm volatile("cp.async.wait_group 1;" ::: "memory");
    __syncthreads();

    uint32_t qf[4][4];
    {
        const uint32_t aoff = (uint32_t)((wid * 16 + (lane & 15)) * FAS + (lane >> 4) * 16);
#pragma unroll
        for (int ks = 0; ks < 4; ++ks)
            LDSM4(qf[ks], qbase + aoff + ks * 32);
    }

    uint32_t koff[8];
#pragma unroll
    for (int p = 0; p < 8; ++p)
        koff[p] = (uint32_t)((p * 16 + ((lane >> 4) << 3) + (lane & 7)) * FAS
                             + ((lane >> 3) & 1) * 16);
    const int vg = lane >> 3;
    const uint32_t voff_r = (uint32_t)(((vg & 1) * 8 + (lane & 7)) * FAS + (vg >> 1) * 16);

    float O[8][4];
#pragma unroll
    for (int j = 0; j < 8; ++j)
#pragma unroll
        for (int r = 0; r < 4; ++r) O[j][r] = 0.0f;
    float m0 = -1e30f, m1 = -1e30f, l0 = 0.0f, l1 = 0.0f;

    const int r_lo = lane >> 2, c_lo = (lane & 3) * 2;
    const int row_loc0 = wid * 16 + r_lo;
    const int row_loc1 = row_loc0 + 8;

    for (int kt = 0; kt <= qi; ++kt) {
        if (kt + 1 <= qi) {
            LOADKV(kt + 1, (kt + 1) & 1);
            asm volatile("cp.async.wait_group 1;" ::: "memory");
        } else {
            asm volatile("cp.async.wait_group 0;" ::: "memory");
        }
        __syncthreads();

        const uint32_t sK = base + (kt & 1) * KVST;
        const uint32_t sV = sK + FTILE;

        // ---- S = Qh K^T
        float s[16][4];
#pragma unroll
        for (int j = 0; j < 16; ++j)
#pragma unroll
            for (int r = 0; r < 4; ++r) s[j][r] = 0.0f;

#pragma unroll
        for (int ks = 0; ks < 4; ++ks) {
#pragma unroll
            for (int p = 0; p < 8; ++p) {
                uint32_t kb[4];
                LDSM4(kb, sK + koff[p] + ks * 32);
#pragma unroll
                for (int j = 0; j < 2; ++j)
                    MMA_F16(s[2 * p + j], qf[ks], &kb[j * 2]);
            }
        }

        if (kt == qi) {
#pragma unroll
            for (int n8 = 0; n8 < 16; ++n8) {
                const int c0 = n8 * 8 + c_lo;
                if (c0 > row_loc0)     s[n8][0] = -1e30f;
                if (c0 + 1 > row_loc0) s[n8][1] = -1e30f;
                if (c0 > row_loc1)     s[n8][2] = -1e30f;
                if (c0 + 1 > row_loc1) s[n8][3] = -1e30f;
            }
        }

        float mx0 = -1e30f, mx1 = -1e30f;
#pragma unroll
        for (int j = 0; j < 16; ++j) {
            mx0 = fmaxf(mx0, fmaxf(s[j][0], s[j][1]));
            mx1 = fmaxf(mx1, fmaxf(s[j][2], s[j][3]));
        }
#pragma unroll
        for (int off = 1; off <= 2; off <<= 1) {
            mx0 = fmaxf(mx0, __shfl_xor_sync(0xffffffffu, mx0, off, 32));
            mx1 = fmaxf(mx1, __shfl_xor_sync(0xffffffffu, mx1, off, 32));
        }
        const float mn0 = fmaxf(m0, mx0), mn1 = fmaxf(m1, mx1);
        const float cr0 = exp2f(m0 - mn0), cr1 = exp2f(m1 - mn1);
        float sum0 = 0.0f, sum1 = 0.0f;
#pragma unroll
        for (int j = 0; j < 16; ++j) {
            s[j][0] = exp2f(s[j][0] - mn0); sum0 += s[j][0];
            s[j][1] = exp2f(s[j][1] - mn0); sum0 += s[j][1];
            s[j][2] = exp2f(s[j][2] - mn1); sum1 += s[j][2];
            s[j][3] = exp2f(s[j][3] - mn1); sum1 += s[j][3];
        }
#pragma unroll
        for (int off = 1; off <= 2; off <<= 1) {
            sum0 += __shfl_xor_sync(0xffffffffu, sum0, off, 32);
            sum1 += __shfl_xor_sync(0xffffffffu, sum1, off, 32);
        }
        l0 = l0 * cr0 + sum0; l1 = l1 * cr1 + sum1;
        m0 = mn0; m1 = mn1;
#pragma unroll
        for (int j = 0; j < 8; ++j) {
            O[j][0] *= cr0; O[j][1] *= cr0; O[j][2] *= cr1; O[j][3] *= cr1;
        }

        // ---- O += Ph V
#pragma unroll
        for (int ks2 = 0; ks2 < 8; ++ks2) {
            uint32_t af[4];
            af[0] = pack_h2(s[2 * ks2][0],     s[2 * ks2][1]);
            af[1] = pack_h2(s[2 * ks2][2],     s[2 * ks2][3]);
            af[2] = pack_h2(s[2 * ks2 + 1][0], s[2 * ks2 + 1][1]);
            af[3] = pack_h2(s[2 * ks2 + 1][2], s[2 * ks2 + 1][3]);
            const uint32_t vrow = voff_r + ks2 * 16 * FAS;
#pragma unroll
            for (int j2 = 0; j2 < 4; ++j2) {
                uint32_t vb[4];
                LDSM4T(vb, sV + vrow + j2 * 32);
#pragma unroll
                for (int j = 0; j < 2; ++j)
                    MMA_F16(O[2 * j2 + j], af, &vb[j * 2]);
            }
        }
        __syncthreads();
    }

    // epilogue: normalize, single fp16 out
    const float inv0 = 1.0f / l0, inv1 = 1.0f / l1;
    const int grow0 = rowQ0 + row_loc0;
    const int grow1 = rowQ0 + row_loc1;
#pragma unroll
    for (int n8 = 0; n8 < 8; ++n8) {
        const int col = h * HEAD_DIM + n8 * 8 + c_lo;
        *(uint32_t*)(att_h + (size_t)grow0 * D_MODEL + col) =
            pack_h2(O[n8][0] * inv0, O[n8][1] * inv0);
        *(uint32_t*)(att_h + (size_t)grow1 * D_MODEL + col) =
            pack_h2(O[n8][2] * inv1, O[n8][3] * inv1);
    }
#undef LOADKV
}

// ---------------------------------------------------------------------------
extern "C" void kernel_launch(void* const* d_in, const int* in_sizes, int n_in,
                              void* d_out, int out_size) {
    const float* x     = (const float*)d_in[0];
    const float* W_qkv = (const float*)d_in[1];
    const float* W_out = (const float*)d_in[2];
    float*       out   = (float*)d_out;

    __half *qh, *xh, *wq, *wo, *ath;
    cudaGetSymbolAddress((void**)&qh,  g_qkv_h);
    cudaGetSymbolAddress((void**)&xh,  g_x_h);
    cudaGetSymbolAddress((void**)&wq,  g_wqkv_h);
    cudaGetSymbolAddress((void**)&wo,  g_wout_h);
    cudaGetSymbolAddress((void**)&ath, g_att_h);

    static cudaStream_t s2 = nullptr;
    static cudaEvent_t evFork, evWo;
    if (s2 == nullptr) {
        cudaStreamCreateWithFlags(&s2, cudaStreamNonBlocking);
        cudaEventCreateWithFlags(&evFork, cudaEventDisableTiming);
        cudaEventCreateWithFlags(&evWo, cudaEventDisableTiming);
    }

    const int smem_gemm = 2 * SST;                     // 40960
    const int smem_attn = 2 * KVST + FTILE;            // 92160
    cudaFuncSetAttribute((const void*)f16_gemm_t<true>,
                         cudaFuncAttributeMaxDynamicSharedMemorySize, smem_gemm);
    cudaFuncSetAttribute((const void*)f16_gemm_t<false>,
                         cudaFuncAttributeMaxDynamicSharedMemorySize, smem_gemm);
    cudaFuncSetAttribute(flash_attn_tc, cudaFuncAttributeMaxDynamicSharedMemorySize, smem_attn);

    const float qscale = 0.125f * 1.4426950408889634f;  // fold log2(e) for exp2 softmax

    // W_out transpose off the critical path (only G3 consumes it)
    cudaEventRecord(evFork, 0);
    cudaStreamWaitEvent(s2, evFork, 0);
    transpose_f16<<<dim3(D_MODEL / 32, D_MODEL / 32), dim3(32, 8), 0, s2>>>(
        W_out, wo, D_MODEL, D_MODEL, 0, 1.0f);
    cudaEventRecord(evWo, s2);

    cvt_x_f16<<<(M_ROWS * D_MODEL / 4 + 255) / 256, 256>>>(
        (const float4*)x, xh, M_ROWS * D_MODEL / 4);
    transpose_f16<<<dim3(QKV_N / 32, D_MODEL / 32), dim3(32, 8)>>>(
        W_qkv, wq, D_MODEL, QKV_N, D_MODEL, qscale);

    // 1) qkv = x_h @ W_qkv  (fp16 out)
    f16_gemm_t<true><<<dim3(QKV_N / 128, M_ROWS / 128), 128, smem_gemm>>>(
        xh, wq, nullptr, qh, M_ROWS, QKV_N, D_MODEL);

    // 2) causal flash attention (fp16 out, 2 CTAs/SM)
    flash_attn_tc<<<dim3(T_SEQ / 128, B_SZ * N_HEADS), 256, smem_attn>>>(qh, ath);

    // 3) out = att_h @ W_out  (fp32 out) — after W_out transpose completes
    cudaStreamWaitEvent(0, evWo, 0);
    f16_gemm_t<false><<<dim3(D_MODEL / 128, M_ROWS / 128), 128, smem_gemm>>>(
        ath, wo, out, nullptr, M_ROWS, D_MODEL, D_MODEL);
}

// round 16
// speedup vs baseline: 1.0438x; 1.0438x over previous
#include <cuda_runtime.h>
#include <cuda_fp16.h>
#include <math.h>
#include <cstdint>

#define D_MODEL   1024
#define T_SEQ     2048
#define B_SZ      4
#define N_HEADS   16
#define HEAD_DIM  64
#define M_ROWS    8192
#define QKV_N     3072

// Scratch (no cudaMalloc allowed)
__device__ __half  g_qkv_h[(size_t)M_ROWS * QKV_N];
__device__ __half  g_x_h[(size_t)M_ROWS * D_MODEL];
__device__ __half  g_att_h[(size_t)M_ROWS * D_MODEL];
__device__ __half  g_wqkv_h[(size_t)QKV_N * D_MODEL];
__device__ __half  g_wout_h[(size_t)D_MODEL * D_MODEL];

__device__ __forceinline__ uint32_t smem_u32(const void* p) {
    uint32_t a;
    asm("{ .reg .u64 t; cvta.to.shared.u64 t, %1; cvt.u32.u64 %0, t; }" : "=r"(a) : "l"(p));
    return a;
}
__device__ __forceinline__ uint32_t pack_h2(float a, float b) {
    __half2 v = __floats2half2_rn(a, b);
    return *reinterpret_cast<uint32_t*>(&v);
}

#define LDSM4(r, addr) \
    asm volatile("ldmatrix.sync.aligned.m8n8.x4.shared.b16 {%0,%1,%2,%3}, [%4];" \
        : "=r"((r)[0]), "=r"((r)[1]), "=r"((r)[2]), "=r"((r)[3]) : "r"(addr))
#define LDSM4T(r, addr) \
    asm volatile("ldmatrix.sync.aligned.m8n8.x4.trans.shared.b16 {%0,%1,%2,%3}, [%4];" \
        : "=r"((r)[0]), "=r"((r)[1]), "=r"((r)[2]), "=r"((r)[3]) : "r"(addr))

#define MMA_F16(d, a, b) \
    asm volatile("mma.sync.aligned.m16n8k16.row.col.f32.f16.f16.f32 " \
        "{%0,%1,%2,%3}, {%4,%5,%6,%7}, {%8,%9}, {%0,%1,%2,%3};" \
        : "+f"((d)[0]), "+f"((d)[1]), "+f"((d)[2]), "+f"((d)[3]) \
        : "r"((a)[0]), "r"((a)[1]), "r"((a)[2]), "r"((a)[3]), "r"((b)[0]), "r"((b)[1]))

#define CP16(dst, src) \
    asm volatile("cp.async.cg.shared.global [%0], [%1], 16;" :: "r"(dst), "l"(src) : "memory")
#define CP_COMMIT() asm volatile("cp.async.commit_group;" ::: "memory")

// ---------------------------------------------------------------------------
__global__ void cvt_x_f16(const float4* __restrict__ x,
                          __half* __restrict__ hi, int n4) {
    const int i = blockIdx.x * 256 + threadIdx.x;
    if (i >= n4) return;
    float4 v = x[i];
    uint32_t* hp = reinterpret_cast<uint32_t*>(hi) + 2 * i;
    hp[0] = pack_h2(v.x, v.y);
    hp[1] = pack_h2(v.z, v.w);
}

__global__ void transpose_f16(const float* __restrict__ W,
                              __half* __restrict__ Wt,
                              int Kr, int Nc, int scale_lim, float scale) {
    __shared__ float tile[32][33];
    const int bx = blockIdx.x * 32, by = blockIdx.y * 32;
    const int tx = threadIdx.x, ty = threadIdx.y;
#pragma unroll
    for (int u = 0; u < 32; u += 8)
        tile[ty + u][tx] = W[(size_t)(by + ty + u) * Nc + bx + tx];
    __syncthreads();
#pragma unroll
    for (int u = 0; u < 32; u += 8) {
        const int n = bx + ty + u;
        float v = tile[tx][ty + u];
        if (n < scale_lim) v *= scale;
        Wt[(size_t)n * Kr + by + tx] = __float2half_rn(v);
    }
}

// ---------------------------------------------------------------------------
// Single-term fp16 GEMM: C = A @ B^T  (fp32 acc).
// CTA 128x128, 128 threads, 4 warps 64x64; K-panel 32, 2-stage cp.async.
// ---------------------------------------------------------------------------
#define PANEL    32
#define RSTRIDE  80
#define TILE_B   (128 * RSTRIDE)        // 10240
#define SST      (2 * TILE_B)           // A, B per stage

template<bool F16OUT>
__global__ __launch_bounds__(128, 2) void f16_gemm_t(const __half* __restrict__ A,
                                                     const __half* __restrict__ B,
                                                     float* __restrict__ C,
                                                     __half* __restrict__ Ch,
                                                     int M, int N, int K) {
    extern __shared__ char sm[];
    const uint32_t base = smem_u32(sm);

    const int t = threadIdx.x;
    const int wid = t >> 5, lane = t & 31;
    const int m0 = blockIdx.y * 128, n0 = blockIdx.x * 128;
    const int wm = (wid >> 1) * 64, wn = (wid & 1) * 64;
    const int NKI = K / PANEL;

    const int rg = t >> 2, sg = t & 3;
    const uint32_t s_off = (uint32_t)(rg * RSTRIDE + sg * 16);

    auto load_stage = [&](int i, int s) {
        const size_t k0 = (size_t)i * PANEL + sg * 8;
        const uint32_t st = base + s * SST + s_off;
#pragma unroll
        for (int u = 0; u < 4; ++u) {
            const int r = rg + u * 32;
            const uint32_t so = st + u * 32 * RSTRIDE;
            CP16(so,          A + (size_t)(m0 + r) * K + k0);
            CP16(so + TILE_B, B + (size_t)(n0 + r) * K + k0);
        }
        CP_COMMIT();
    };

    uint32_t aoff[4], boff[4];
#pragma unroll
    for (int mt = 0; mt < 4; ++mt)
        aoff[mt] = (uint32_t)((wm + mt * 16 + (lane & 15)) * RSTRIDE + (lane >> 4) * 16);
#pragma unroll
    for (int p = 0; p < 4; ++p)
        boff[p] = (uint32_t)((wn + p * 16 + ((lane >> 4) << 3) + (lane & 7)) * RSTRIDE
                             + ((lane >> 3) & 1) * 16);

    float acc[4][8][4];
#pragma unroll
    for (int i = 0; i < 4; ++i)
#pragma unroll
        for (int j = 0; j < 8; ++j)
#pragma unroll
            for (int r = 0; r < 4; ++r) acc[i][j][r] = 0.0f;

    load_stage(0, 0);

    for (int i = 0; i < NKI; ++i) {
        if (i + 1 < NKI) {
            load_stage(i + 1, (i + 1) & 1);
            asm volatile("cp.async.wait_group 1;" ::: "memory");
        } else {
            asm volatile("cp.async.wait_group 0;" ::: "memory");
        }
        __syncthreads();

        const uint32_t sA = base + (i & 1) * SST;
        const uint32_t sB = sA + TILE_B;

#pragma unroll
        for (int ks = 0; ks < 2; ++ks) {
            uint32_t af[4][4];
#pragma unroll
            for (int mt = 0; mt < 4; ++mt)
                LDSM4(af[mt], sA + aoff[mt] + ks * 32);
#pragma unroll
            for (int p = 0; p < 4; ++p) {
                uint32_t bf[4];
                LDSM4(bf, sB + boff[p] + ks * 32);
#pragma unroll
                for (int j = 0; j < 2; ++j)
#pragma unroll
                    for (int mt = 0; mt < 4; ++mt)
                        MMA_F16(acc[mt][2 * p + j], af[mt], &bf[j * 2]);
            }
        }
        __syncthreads();
    }

    const int r_lo = lane >> 2, c_lo = (lane & 3) * 2;
#pragma unroll
    for (int mt = 0; mt < 4; ++mt) {
        const int row = m0 + wm + mt * 16 + r_lo;
#pragma unroll
        for (int n8 = 0; n8 < 8; ++n8) {
            const int col = n0 + wn + n8 * 8 + c_lo;
            if constexpr (F16OUT) {
                *(uint32_t*)(Ch + (size_t)row * N + col) =
                    pack_h2(acc[mt][n8][0], acc[mt][n8][1]);
                *(uint32_t*)(Ch + (size_t)(row + 8) * N + col) =
                    pack_h2(acc[mt][n8][2], acc[mt][n8][3]);
            } else {
                *(float2*)(C + (size_t)row * N + col) =
                    make_float2(acc[mt][n8][0], acc[mt][n8][1]);
                *(float2*)(C + (size_t)(row + 8) * N + col) =
                    make_float2(acc[mt][n8][2], acc[mt][n8][3]);
            }
        }
    }
}

// ---------------------------------------------------------------------------
// Tensor-core flash attention, single-fp16 operands.
// q-tile 64 rows / 128 threads / 4 warps -> 2 CTAs/SM WITHOUT a register cap
// (per-warp fragment layout identical to the proven 128-row version).
// k-tile 128, double-buffered K/V.
// ---------------------------------------------------------------------------
#define FAS    144
#define FTILE  (128 * FAS)              // K or V tile (128 rows)
#define QTILE  (64 * FAS)               // Q tile (64 rows)
#define KVST   (2 * FTILE)              // Kh, Vh per stage

__global__ __launch_bounds__(128, 2) void flash_attn_tc(
    const __half* __restrict__ qkvh,
    __half* __restrict__ att_h) {
    extern __shared__ char sm[];
    const uint32_t base  = smem_u32(sm);
    const uint32_t qbase = base + 2 * KVST;

    const int qi = (int)gridDim.x - 1 - (int)blockIdx.x;   // 0..31, big first
    const int bh = blockIdx.y;
    const int b  = bh >> 4, h = bh & 15;
    const int t  = threadIdx.x;
    const int wid = t >> 5, lane = t & 31;

    const int rowQ0 = b * T_SEQ + qi * 64;
    const int colQ = h * HEAD_DIM;
    const int colK = D_MODEL + h * HEAD_DIM;
    const int colV = 2 * D_MODEL + h * HEAD_DIM;

    const int rg = t >> 3, sg = t & 7;               // rg 0..15, sg 0..7
    const uint32_t ls_off = (uint32_t)(rg * FAS + sg * 16);

    const int kt_max = (qi * 64 + 63) >> 7;          // last (only masked) k-tile

#define LOADKV(kt, s) do { \
        const uint32_t _st = base + (s) * KVST + ls_off; \
        _Pragma("unroll") \
        for (int _u = 0; _u < 8; ++_u) { \
            const int _r = rg + _u * 16; \
            const size_t _row = (size_t)(b * T_SEQ + (kt) * 128 + _r) * QKV_N; \
            const uint32_t _so = _st + _u * 16 * FAS; \
            CP16(_so,         qkvh + _row + colK + sg * 8); \
            CP16(_so + FTILE, qkvh + _row + colV + sg * 8); \
        } \
        CP_COMMIT(); \
    } while (0)

    {   // Q tile: 64 rows
#pragma unroll
        for (int u = 0; u < 4; ++u) {
            const int r = rg + u * 16;
            const size_t row = (size_t)(rowQ0 + r) * QKV_N;
            CP16(qbase + ls_off + u * 16 * FAS, qkvh + row + colQ + sg * 8);
        }
        CP_COMMIT();
    }
    LOADKV(0, 0);

    asm volatile("cp.async.wait_group 1;" ::: "memory");
    __syncthreads();

    uint32_t qf[4][4];
    {
        const uint32_t aoff = (uint32_t)((wid * 16 + (lane & 15)) * FAS + (lane >> 4) * 16);
#pragma unroll
        for (int ks = 0; ks < 4; ++ks)
            LDSM4(qf[ks], qbase + aoff + ks * 32);
    }

    uint32_t koff[8];
#pragma unroll
    for (int p = 0; p < 8; ++p)
        koff[p] = (uint32_t)((p * 16 + ((lane >> 4) << 3) + (lane & 7)) * FAS
                             + ((lane >> 3) & 1) * 16);
    const int vg = lane >> 3;
    const uint32_t voff_r = (uint32_t)(((vg & 1) * 8 + (lane & 7)) * FAS + (vg >> 1) * 16);

    float O[8][4];
#pragma unroll
    for (int j = 0; j < 8; ++j)
#pragma unroll
        for (int r = 0; r < 4; ++r) O[j][r] = 0.0f;
    float m0 = -1e30f, m1 = -1e30f, l0 = 0.0f, l1 = 0.0f;

    const int r_lo = lane >> 2, c_lo = (lane & 3) * 2;
    const int qrow_g0 = qi * 64 + wid * 16 + r_lo;   // global (in-batch) q rows
    const int qrow_g1 = qrow_g0 + 8;

    for (int kt = 0; kt <= kt_max; ++kt) {
        if (kt + 1 <= kt_max) {
            LOADKV(kt + 1, (kt + 1) & 1);
            asm volatile("cp.async.wait_group 1;" ::: "memory");
        } else {
            asm volatile("cp.async.wait_group 0;" ::: "memory");
        }
        __syncthreads();

        const uint32_t sK = base + (kt & 1) * KVST;
        const uint32_t sV = sK + FTILE;

        // ---- S = Qh K^T
        float s[16][4];
#pragma unroll
        for (int j = 0; j < 16; ++j)
#pragma unroll
            for (int r = 0; r < 4; ++r) s[j][r] = 0.0f;

#pragma unroll
        for (int ks = 0; ks < 4; ++ks) {
#pragma unroll
            for (int p = 0; p < 8; ++p) {
                uint32_t kb[4];
                LDSM4(kb, sK + koff[p] + ks * 32);
#pragma unroll
                for (int j = 0; j < 2; ++j)
                    MMA_F16(s[2 * p + j], qf[ks], &kb[j * 2]);
            }
        }

        // ---- causal mask (only last k-tile can touch the diagonal)
        if (kt == kt_max) {
            const int kbase = kt * 128;
#pragma unroll
            for (int n8 = 0; n8 < 16; ++n8) {
                const int kc = kbase + n8 * 8 + c_lo;
                if (kc > qrow_g0)     s[n8][0] = -1e30f;
                if (kc + 1 > qrow_g0) s[n8][1] = -1e30f;
                if (kc > qrow_g1)     s[n8][2] = -1e30f;
                if (kc + 1 > qrow_g1) s[n8][3] = -1e30f;
            }
        }

        float mx0 = -1e30f, mx1 = -1e30f;
#pragma unroll
        for (int j = 0; j < 16; ++j) {
            mx0 = fmaxf(mx0, fmaxf(s[j][0], s[j][1]));
            mx1 = fmaxf(mx1, fmaxf(s[j][2], s[j][3]));
        }
#pragma unroll
        for (int off = 1; off <= 2; off <<= 1) {
            mx0 = fmaxf(mx0, __shfl_xor_sync(0xffffffffu, mx0, off, 32));
            mx1 = fmaxf(mx1, __shfl_xor_sync(0xffffffffu, mx1, off, 32));
        }
        const float mn0 = fmaxf(m0, mx0), mn1 = fmaxf(m1, mx1);
        const float cr0 = exp2f(m0 - mn0), cr1 = exp2f(m1 - mn1);
        float sum0 = 0.0f, sum1 = 0.0f;
#pragma unroll
        for (int j = 0; j < 16; ++j) {
            s[j][0] = exp2f(s[j][0] - mn0); sum0 += s[j][0];
            s[j][1] = exp2f(s[j][1] - mn0); sum0 += s[j][1];
            s[j][2] = exp2f(s[j][2] - mn1); sum1 += s[j][2];
            s[j][3] = exp2f(s[j][3] - mn1); sum1 += s[j][3];
        }
#pragma unroll
        for (int off = 1; off <= 2; off <<= 1) {
            sum0 += __shfl_xor_sync(0xffffffffu, sum0, off, 32);
            sum1 += __shfl_xor_sync(0xffffffffu, sum1, off, 32);
        }
        l0 = l0 * cr0 + sum0; l1 = l1 * cr1 + sum1;
        m0 = mn0; m1 = mn1;
#pragma unroll
        for (int j = 0; j < 8; ++j) {
            O[j][0] *= cr0; O[j][1] *= cr0; O[j][2] *= cr1; O[j][3] *= cr1;
        }

        // ---- O += Ph V
#pragma unroll
        for (int ks2 = 0; ks2 < 8; ++ks2) {
            uint32_t af[4];
            af[0] = pack_h2(s[2 * ks2][0],     s[2 * ks2][1]);
            af[1] = pack_h2(s[2 * ks2][2],     s[2 * ks2][3]);
            af[2] = pack_h2(s[2 * ks2 + 1][0], s[2 * ks2 + 1][1]);
            af[3] = pack_h2(s[2 * ks2 + 1][2], s[2 * ks2 + 1][3]);
            const uint32_t vrow = voff_r + ks2 * 16 * FAS;
#pragma unroll
            for (int j2 = 0; j2 < 4; ++j2) {
                uint32_t vb[4];
                LDSM4T(vb, sV + vrow + j2 * 32);
#pragma unroll
                for (int j = 0; j < 2; ++j)
                    MMA_F16(O[2 * j2 + j], af, &vb[j * 2]);
            }
        }
        __syncthreads();
    }

    // epilogue: normalize, single fp16 out
    const float inv0 = 1.0f / l0, inv1 = 1.0f / l1;
    const int grow0 = b * T_SEQ + qrow_g0;
    const int grow1 = b * T_SEQ + qrow_g1;
#pragma unroll
    for (int n8 = 0; n8 < 8; ++n8) {
        const int col = h * HEAD_DIM + n8 * 8 + c_lo;
        *(uint32_t*)(att_h + (size_t)grow0 * D_MODEL + col) =
            pack_h2(O[n8][0] * inv0, O[n8][1] * inv0);
        *(uint32_t*)(att_h + (size_t)grow1 * D_MODEL + col) =
            pack_h2(O[n8][2] * inv1, O[n8][3] * inv1);
    }
#undef LOADKV
}

// ---------------------------------------------------------------------------
extern "C" void kernel_launch(void* const* d_in, const int* in_sizes, int n_in,
                              void* d_out, int out_size) {
    const float* x     = (const float*)d_in[0];
    const float* W_qkv = (const float*)d_in[1];
    const float* W_out = (const float*)d_in[2];
    float*       out   = (float*)d_out;

    __half *qh, *xh, *wq, *wo, *ath;
    cudaGetSymbolAddress((void**)&qh,  g_qkv_h);
    cudaGetSymbolAddress((void**)&xh,  g_x_h);
    cudaGetSymbolAddress((void**)&wq,  g_wqkv_h);
    cudaGetSymbolAddress((void**)&wo,  g_wout_h);
    cudaGetSymbolAddress((void**)&ath, g_att_h);

    const int smem_gemm = 2 * SST;                     // 40960
    const int smem_attn = 2 * KVST + QTILE;            // 82944
    cudaFuncSetAttribute((const void*)f16_gemm_t<true>,
                         cudaFuncAttributeMaxDynamicSharedMemorySize, smem_gemm);
    cudaFuncSetAttribute((const void*)f16_gemm_t<false>,
                         cudaFuncAttributeMaxDynamicSharedMemorySize, smem_gemm);
    cudaFuncSetAttribute(flash_attn_tc, cudaFuncAttributeMaxDynamicSharedMemorySize, smem_attn);

    const float qscale = 0.125f * 1.4426950408889634f;  // fold log2(e) for exp2 softmax
    cvt_x_f16<<<(M_ROWS * D_MODEL / 4 + 255) / 256, 256>>>(
        (const float4*)x, xh, M_ROWS * D_MODEL / 4);
    transpose_f16<<<dim3(QKV_N / 32, D_MODEL / 32), dim3(32, 8)>>>(
        W_qkv, wq, D_MODEL, QKV_N, D_MODEL, qscale);
    transpose_f16<<<dim3(D_MODEL / 32, D_MODEL / 32), dim3(32, 8)>>>(
        W_out, wo, D_MODEL, D_MODEL, 0, 1.0f);

    // 1) qkv = x_h @ W_qkv  (fp16 out)
    f16_gemm_t<true><<<dim3(QKV_N / 128, M_ROWS / 128), 128, smem_gemm>>>(
        xh, wq, nullptr, qh, M_ROWS, QKV_N, D_MODEL);

    // 2) causal flash attention (64-row q-tiles, 2 CTAs/SM, no reg cap)
    flash_attn_tc<<<dim3(T_SEQ / 64, B_SZ * N_HEADS), 128, smem_attn>>>(qh, ath);

    // 3) out = att_h @ W_out  (fp32 out)
    f16_gemm_t<false><<<dim3(D_MODEL / 128, M_ROWS / 128), 128, smem_gemm>>>(
        ath, wo, out, nullptr, M_ROWS, D_MODEL, D_MODEL);
}